// round 3
// baseline (speedup 1.0000x reference)
#include <cuda_runtime.h>
#include <cuda_bf16.h>
#include <cstdint>

// ============================================================================
// AdaptiveLogSoftmax on GB300 — round 3: tf32 mma.sync GEMM + fused logsumexp,
// 4-stage cp.async pipeline, 16B-aligned dynamic smem (fixes r2 cp.async bug).
//
// nll(t) = (lse_head - z_head[need])  [+ (lse_tail_c - z_tail[local]) if tail]
// need = target (shortlist) or head gate column S+3-c.
// Logits are O(1) -> sum exp(z) directly in fp32, no max pass.
// ============================================================================

#define MAXNT    4096
#define TM       128
#define TN       128
#define KT       16
#define KSTRIDE  20          // 16 + 4 pad: (20*m + k) % 32 distinct for m<8,k<8
#define NSTAGE   4
#define NTHREADS 256

#define A_STAGE_FLOATS (TM * KSTRIDE)               // 2560 floats = 10240 B
#define STAGE_FLOATS   (2 * A_STAGE_FLOATS)         // A + B per stage, 20480 B
#define SMEM_BYTES     (NSTAGE * STAGE_FLOATS * 4)  // 81920 B

__device__ int   g_cluster[MAXNT];
__device__ int   g_localt [MAXNT];
__device__ int   g_need   [MAXNT];
__device__ int   g_counts [4];
__device__ int   g_list   [3 * MAXNT];
__device__ float g_se_head[MAXNT];
__device__ float g_se_tail[MAXNT];
__device__ float g_lg_head[MAXNT];
__device__ float g_lg_tail[MAXNT];

// ----------------------------------------------------------------------------
__device__ __forceinline__ uint32_t cvt_tf32(float x) {
    uint32_t r;
    asm("cvt.rna.tf32.f32 %0, %1;" : "=r"(r) : "f"(x));
    return r;
}
__device__ __forceinline__ uint32_t smem_u32(const void* p) {
    return (uint32_t)__cvta_generic_to_shared(p);
}
__device__ __forceinline__ void cp16(uint32_t dst, const void* src) {
    asm volatile("cp.async.cg.shared.global [%0], [%1], 16;" :: "r"(dst), "l"(src));
}

// ----------------------------------------------------------------------------
// Prep: detect target dtype (int32 vs int64), classify tokens, build lists.
// ----------------------------------------------------------------------------
__global__ void prep_kernel(const int* __restrict__ traw, int NT,
                            int S, int C1, int C2)
{
    __shared__ int s_nonzero;
    const int tid = threadIdx.x;
    if (tid == 0) s_nonzero = 0;
    if (tid < 4) g_counts[tid] = 0;
    __syncthreads();

    // int64 little-endian: odd 32-bit words within the first NT words are the
    // all-zero high halves. int32: they are target values (never all zero).
    for (int i = tid; i < NT; i += blockDim.x)
        if ((i & 1) && traw[i] != 0) s_nonzero = 1;
    __syncthreads();
    const bool is64 = (s_nonzero == 0);
    const long long* t64 = (const long long*)traw;

    for (int t = tid; t < NT; t += blockDim.x) {
        int tg = is64 ? (int)t64[t] : traw[t];
        int c  = (tg < S) ? 0 : (tg < C1) ? 1 : (tg < C2) ? 2 : 3;
        int lo = (c == 0) ? 0 : (c == 1) ? S : (c == 2) ? C1 : C2;
        g_cluster[t] = c;
        g_localt [t] = tg - lo;
        g_need   [t] = (c == 0) ? tg : (S + 3 - c);   // head_logprob[:, -c]
        g_se_head[t] = 0.f;
        g_se_tail[t] = 0.f;
        g_lg_head[t] = 0.f;
        g_lg_tail[t] = 0.f;
        if (c > 0) {
            int m = atomicAdd(&g_counts[c], 1);
            g_list[(c - 1) * MAXNT + m] = t;
        }
    }
}

// ----------------------------------------------------------------------------
// Fused tf32 tensor-core GEMM + exp-sum + target-logit gather.
// Block tile 128x128, K-tile 16, 4-stage cp.async ring.
// 8 warps in a 2(M) x 4(N) grid; each warp 64x32 via m16n8k8 tf32 mma.
// Grid.x = row tiles (fast-varying) so one wave shares each B col-tile in L2.
// ----------------------------------------------------------------------------
extern __shared__ float smem[];   // [NSTAGE][ A:TM*KSTRIDE | B:TN*KSTRIDE ]

__global__ void __launch_bounds__(NTHREADS, 2)
gemm_lse_tc(const float* __restrict__ hidden,
            const float* __restrict__ weight,
            const float* __restrict__ bias,
            const float* __restrict__ cweight,
            const float* __restrict__ cbias,
            int D, int NT, int cluster, int class_lo, int ncols, int S)
{
    const int tid   = threadIdx.x;
    const int count = (cluster == 0) ? NT : g_counts[cluster];
    const int row_base = blockIdx.x * TM;
    if (row_base >= count) return;
    const int col_base = blockIdx.y * TN;

    // ---- global sources: thread pair (t>>1)=row/col index, (t&1)*8 = k off
    const int lrow = tid >> 1;
    const int lk   = (tid & 1) * 8;

    int a_m = row_base + lrow;
    int a_token;
    if (cluster == 0) a_token = (a_m < NT) ? a_m : 0;
    else              a_token = g_list[(cluster - 1) * MAXNT +
                                       ((a_m < count) ? a_m : 0)];
    const float* a_src = hidden + (size_t)a_token * D + lk;

    int b_n = col_base + lrow;
    int gj  = (b_n < ncols) ? b_n : 0;
    const float* b_src;
    if (cluster == 0) b_src = (gj < S) ? (weight  + (size_t)gj * D)
                                       : (cweight + (size_t)(gj - S) * D);
    else              b_src = weight + (size_t)(class_lo + gj) * D;
    b_src += lk;

    // smem destinations per stage (all offsets multiples of 16 B)
    uint32_t smem_base = smem_u32(smem);
    uint32_t aDst[NSTAGE], bDst[NSTAGE];
    #pragma unroll
    for (int s = 0; s < NSTAGE; s++) {
        aDst[s] = smem_base + (s * STAGE_FLOATS + lrow * KSTRIDE + lk) * 4;
        bDst[s] = aDst[s] + A_STAGE_FLOATS * 4;
    }

    // ---- warp / lane geometry
    const int wid  = tid >> 5;
    const int lane = tid & 31;
    const int wm   = (wid & 1) * 64;    // warp M offset in tile
    const int wn   = (wid >> 1) * 32;   // warp N offset in tile
    const int qrow = lane >> 2;         // 0..7
    const int qcol = lane & 3;          // 0..3

    float c[4][4][4];
    #pragma unroll
    for (int mi = 0; mi < 4; mi++)
        #pragma unroll
        for (int ni = 0; ni < 4; ni++)
            #pragma unroll
            for (int r = 0; r < 4; r++) c[mi][ni][r] = 0.f;

    const int T = D / KT;   // 64 K-tiles

    // ---- prologue: stages 0..NSTAGE-2
    #pragma unroll
    for (int p = 0; p < NSTAGE - 1; p++) {
        const float* an = a_src + p * KT;
        const float* bn = b_src + p * KT;
        cp16(aDst[p], an); cp16(aDst[p] + 16, an + 4);
        cp16(bDst[p], bn); cp16(bDst[p] + 16, bn + 4);
        asm volatile("cp.async.commit_group;");
    }

    for (int i = 0; i < T; i++) {
        // tiles up to i complete (≤ NSTAGE-2 groups may remain in flight)
        asm volatile("cp.async.wait_group %0;" :: "n"(NSTAGE - 2));
        __syncthreads();

        const int s = i & (NSTAGE - 1);
        const float* As = smem + s * STAGE_FLOATS;
        const float* Bs = As + A_STAGE_FLOATS;

        #pragma unroll
        for (int kk = 0; kk < KT; kk += 8) {
            uint32_t af[4][4];
            #pragma unroll
            for (int mi = 0; mi < 4; mi++) {
                const int r0 = wm + mi * 16 + qrow;
                af[mi][0] = cvt_tf32(As[(r0    ) * KSTRIDE + kk + qcol    ]);
                af[mi][1] = cvt_tf32(As[(r0 + 8) * KSTRIDE + kk + qcol    ]);
                af[mi][2] = cvt_tf32(As[(r0    ) * KSTRIDE + kk + qcol + 4]);
                af[mi][3] = cvt_tf32(As[(r0 + 8) * KSTRIDE + kk + qcol + 4]);
            }
            uint32_t bf[4][2];
            #pragma unroll
            for (int ni = 0; ni < 4; ni++) {
                const int n0 = wn + ni * 8 + qrow;
                bf[ni][0] = cvt_tf32(Bs[n0 * KSTRIDE + kk + qcol    ]);
                bf[ni][1] = cvt_tf32(Bs[n0 * KSTRIDE + kk + qcol + 4]);
            }
            #pragma unroll
            for (int mi = 0; mi < 4; mi++)
                #pragma unroll
                for (int ni = 0; ni < 4; ni++)
                    asm volatile(
                        "mma.sync.aligned.m16n8k8.row.col.f32.tf32.tf32.f32 "
                        "{%0,%1,%2,%3}, {%4,%5,%6,%7}, {%8,%9}, {%0,%1,%2,%3};"
                        : "+f"(c[mi][ni][0]), "+f"(c[mi][ni][1]),
                          "+f"(c[mi][ni][2]), "+f"(c[mi][ni][3])
                        : "r"(af[mi][0]), "r"(af[mi][1]),
                          "r"(af[mi][2]), "r"(af[mi][3]),
                          "r"(bf[ni][0]), "r"(bf[ni][1]));
        }
        __syncthreads();   // stage s fully consumed before it is refilled

        const int nxt = i + NSTAGE - 1;
        if (nxt < T) {
            const int sn = nxt & (NSTAGE - 1);
            const float* an = a_src + nxt * KT;
            const float* bn = b_src + nxt * KT;
            cp16(aDst[sn], an); cp16(aDst[sn] + 16, an + 4);
            cp16(bDst[sn], bn); cp16(bDst[sn] + 16, bn + 4);
        }
        asm volatile("cp.async.commit_group;");   // empty group ok near tail
    }

    // ---- fused epilogue ------------------------------------------------
    float bv[4][2];
    #pragma unroll
    for (int ni = 0; ni < 4; ni++)
        #pragma unroll
        for (int j = 0; j < 2; j++) {
            const int n = col_base + wn + ni * 8 + 2 * qcol + j;
            float b = 0.f;
            if (n < ncols) {
                if (cluster == 0) b = (n < S) ? __ldg(&bias[n])
                                              : __ldg(&cbias[n - S]);
                else              b = __ldg(&bias[class_lo + n]);
            }
            bv[ni][j] = b;
        }

    #pragma unroll
    for (int mi = 0; mi < 4; mi++)
        #pragma unroll
        for (int h = 0; h < 2; h++) {
            const int m = row_base + wm + mi * 16 + qrow + h * 8;
            const bool valid = (m < count);
            int token = 0, needcol = -1;
            if (valid) {
                token   = (cluster == 0) ? m : g_list[(cluster - 1) * MAXNT + m];
                needcol = (cluster == 0) ? g_need[token] : g_localt[token];
            }
            float ssum = 0.f;
            #pragma unroll
            for (int ni = 0; ni < 4; ni++)
                #pragma unroll
                for (int j = 0; j < 2; j++) {
                    const int n = col_base + wn + ni * 8 + 2 * qcol + j;
                    if (n < ncols) {
                        const float z = c[mi][ni][h * 2 + j] + bv[ni][j];
                        ssum += __expf(z);
                        if (valid && n == needcol) {
                            if (cluster == 0) g_lg_head[token] = z;
                            else              g_lg_tail[token] = z;
                        }
                    }
                }
            // quad (qcol 0..3) holds this row's 32 warp columns
            ssum += __shfl_xor_sync(0xffffffffu, ssum, 1);
            ssum += __shfl_xor_sync(0xffffffffu, ssum, 2);
            if (valid && qcol == 0) {
                if (cluster == 0) atomicAdd(&g_se_head[token], ssum);
                else              atomicAdd(&g_se_tail[token], ssum);
            }
        }
}

// ----------------------------------------------------------------------------
__global__ void finalize_kernel(float* __restrict__ out, int NT)
{
    const int t = blockIdx.x * blockDim.x + threadIdx.x;
    if (t >= NT) return;
    float nll = logf(g_se_head[t]) - g_lg_head[t];
    if (g_cluster[t] > 0)
        nll += logf(g_se_tail[t]) - g_lg_tail[t];
    out[t] = nll;
}

// ----------------------------------------------------------------------------
extern "C" void kernel_launch(void* const* d_in, const int* in_sizes, int n_in,
                              void* d_out, int out_size)
{
    const float* hidden  = (const float*)d_in[0];
    const int*   traw    = (const int*)  d_in[1];
    const float* weight  = (const float*)d_in[2];
    const float* bias    = (const float*)d_in[3];
    const float* cweight = (const float*)d_in[4];
    const float* cbias   = (const float*)d_in[5];

    const int NT = out_size;               // one nll per token
    const int D  = in_sizes[0] / NT;       // 1024
    const int NC = in_sizes[3];            // 267735
    const int S = 20000, C1 = 40000, C2 = 200000;

    static bool attr_done = false;
    if (!attr_done) {
        cudaFuncSetAttribute(gemm_lse_tc,
                             cudaFuncAttributeMaxDynamicSharedMemorySize,
                             SMEM_BYTES);
        attr_done = true;
    }

    prep_kernel<<<1, 256>>>(traw, NT, S, C1, C2);

    const int gx = (NT + TM - 1) / TM;     // row tiles (worst case per cluster)

    gemm_lse_tc<<<dim3(gx, (S + 3 + TN - 1) / TN), NTHREADS, SMEM_BYTES>>>(
        hidden, weight, bias, cweight, cbias, D, NT, 0, 0, S + 3, S);
    gemm_lse_tc<<<dim3(gx, (C1 - S + TN - 1) / TN), NTHREADS, SMEM_BYTES>>>(
        hidden, weight, bias, cweight, cbias, D, NT, 1, S, C1 - S, S);
    gemm_lse_tc<<<dim3(gx, (C2 - C1 + TN - 1) / TN), NTHREADS, SMEM_BYTES>>>(
        hidden, weight, bias, cweight, cbias, D, NT, 2, C1, C2 - C1, S);
    gemm_lse_tc<<<dim3(gx, (NC - C2 + TN - 1) / TN), NTHREADS, SMEM_BYTES>>>(
        hidden, weight, bias, cweight, cbias, D, NT, 3, C2, NC - C2, S);

    finalize_kernel<<<(NT + 255) / 256, 256>>>((float*)d_out, NT);
}

// round 5
// speedup vs baseline: 1.2241x; 1.2241x over previous
#include <cuda_runtime.h>
#include <cuda_bf16.h>
#include <cstdint>

// ============================================================================
// AdaptiveLogSoftmax on GB300 — round 5 (= audited round 4): tf32 mma.sync +
// ldmatrix fragment loads, no cvt (HW tf32 truncation), 1 sync/K-tile,
// all 4 GEMMs merged into one launch.
//
// nll(t) = (lse_head - z_head[need])  [+ (lse_tail_c - z_tail[local]) if tail]
// need = target (shortlist) or head gate column S+3-c. Logits are O(1) ->
// sum exp(z) directly in fp32, no max pass.
// ============================================================================

#define MAXNT    4096
#define TM       128
#define TN       128
#define KT       16
#define KSTRIDE  20          // 16 + 4 pad; 80B row stride -> LDSM conflict-free
#define NSTAGE   4
#define NTHREADS 256

#define S_SHORT  20000
#define CUT1     40000
#define CUT2     200000
#define NCLASS   267735

#define A_STAGE_FLOATS (TM * KSTRIDE)               // 2560 floats
#define STAGE_FLOATS   (2 * A_STAGE_FLOATS)         // A + B per stage
#define SMEM_BYTES     (NSTAGE * STAGE_FLOATS * 4)  // 81920 B

__device__ int   g_cluster[MAXNT];
__device__ int   g_localt [MAXNT];
__device__ int   g_need   [MAXNT];
__device__ int   g_counts [4];
__device__ int   g_list   [3 * MAXNT];
__device__ float g_se_head[MAXNT];
__device__ float g_se_tail[MAXNT];
__device__ float g_lg_head[MAXNT];
__device__ float g_lg_tail[MAXNT];

// ----------------------------------------------------------------------------
__device__ __forceinline__ uint32_t smem_u32(const void* p) {
    return (uint32_t)__cvta_generic_to_shared(p);
}
__device__ __forceinline__ void cp16(uint32_t dst, const void* src) {
    asm volatile("cp.async.cg.shared.global [%0], [%1], 16;" :: "r"(dst), "l"(src));
}
__device__ __forceinline__ void ldsm4(uint32_t& r0, uint32_t& r1,
                                      uint32_t& r2, uint32_t& r3, uint32_t a) {
    asm volatile("ldmatrix.sync.aligned.m8n8.x4.shared.b16 {%0,%1,%2,%3}, [%4];"
                 : "=r"(r0), "=r"(r1), "=r"(r2), "=r"(r3) : "r"(a));
}

// ----------------------------------------------------------------------------
__global__ void prep_kernel(const int* __restrict__ traw, int NT)
{
    __shared__ int s_nonzero;
    const int tid = threadIdx.x;
    if (tid == 0) s_nonzero = 0;
    if (tid < 4) g_counts[tid] = 0;
    __syncthreads();

    // int64 LE: odd 32-bit words within the first NT words are zero high
    // halves. int32: they are target values (never all zero in practice).
    for (int i = tid; i < NT; i += blockDim.x)
        if ((i & 1) && traw[i] != 0) s_nonzero = 1;
    __syncthreads();
    const bool is64 = (s_nonzero == 0);
    const long long* t64 = (const long long*)traw;

    for (int t = tid; t < NT; t += blockDim.x) {
        int tg = is64 ? (int)t64[t] : traw[t];
        int c  = (tg < S_SHORT) ? 0 : (tg < CUT1) ? 1 : (tg < CUT2) ? 2 : 3;
        int lo = (c == 0) ? 0 : (c == 1) ? S_SHORT : (c == 2) ? CUT1 : CUT2;
        g_cluster[t] = c;
        g_localt [t] = tg - lo;
        g_need   [t] = (c == 0) ? tg : (S_SHORT + 3 - c);  // head[:, -c]
        g_se_head[t] = 0.f;  g_se_tail[t] = 0.f;
        g_lg_head[t] = 0.f;  g_lg_tail[t] = 0.f;
        if (c > 0) {
            int m = atomicAdd(&g_counts[c], 1);
            g_list[(c - 1) * MAXNT + m] = t;
        }
    }
}

// ----------------------------------------------------------------------------
// One launch covers head (cluster 0) + 3 tail clusters.
// CTA decode: segments [0,e0) head, [e0,e1) c1, [e1,e2) c2, [e2,e3) c3.
// Within a segment, x = row tile (fast) -> a wave shares each B col tile in L2.
// ----------------------------------------------------------------------------
extern __shared__ float smem[];

__global__ void __launch_bounds__(NTHREADS, 2)
gemm_lse_tc(const float* __restrict__ hidden,
            const float* __restrict__ weight,
            const float* __restrict__ bias,
            const float* __restrict__ cweight,
            const float* __restrict__ cbias,
            int D, int NT, int gx, int e0, int e1, int e2)
{
    // ---- segment decode
    const int idx = blockIdx.x;
    int cluster, class_lo, ncols, base;
    if      (idx < e0) { cluster = 0; class_lo = 0;       ncols = S_SHORT + 3;     base = 0;  }
    else if (idx < e1) { cluster = 1; class_lo = S_SHORT; ncols = CUT1 - S_SHORT;  base = e0; }
    else if (idx < e2) { cluster = 2; class_lo = CUT1;    ncols = CUT2 - CUT1;     base = e1; }
    else               { cluster = 3; class_lo = CUT2;    ncols = NCLASS - CUT2;   base = e2; }
    const int li = idx - base;
    const int row_base = (li % gx) * TM;
    const int col_base = (li / gx) * TN;

    const int count = (cluster == 0) ? NT : g_counts[cluster];
    if (row_base >= count) return;

    const int tid = threadIdx.x;

    // ---- global sources: thread pair (t>>1)=row index, (t&1)*8 = k offset
    const int lrow = tid >> 1;
    const int lk   = (tid & 1) * 8;

    int a_m = row_base + lrow;
    int a_token;
    if (cluster == 0) a_token = (a_m < NT) ? a_m : 0;
    else              a_token = g_list[(cluster - 1) * MAXNT +
                                       ((a_m < count) ? a_m : 0)];
    const float* a_src = hidden + (size_t)a_token * D + lk;

    int b_n = col_base + lrow;
    int gj  = (b_n < ncols) ? b_n : 0;
    const float* b_src;
    if (cluster == 0) b_src = (gj < S_SHORT) ? (weight  + (size_t)gj * D)
                                             : (cweight + (size_t)(gj - S_SHORT) * D);
    else              b_src = weight + (size_t)(class_lo + gj) * D;
    b_src += lk;

    const uint32_t smem_base = smem_u32(smem);
    uint32_t aDst[NSTAGE], bDst[NSTAGE];
    #pragma unroll
    for (int s = 0; s < NSTAGE; s++) {
        aDst[s] = smem_base + (s * STAGE_FLOATS + lrow * KSTRIDE + lk) * 4;
        bDst[s] = aDst[s] + A_STAGE_FLOATS * 4;
    }

    // ---- warp / lane geometry
    const int wid  = tid >> 5;
    const int lane = tid & 31;
    const int wm   = (wid & 1) * 64;
    const int wn   = (wid >> 1) * 32;
    const int qrow = lane >> 2;
    const int qcol = lane & 3;

    // ldmatrix per-lane base offsets (floats, within a stage).
    // A x4 @ (mi,kk): matrices {rows +0..7 | +8..15} x {cols kk | kk+4}
    //   lanes 0-7 -> m0, 8-15 -> m1, 16-23 -> m2, 24-31 -> m3.
    const uint32_t aFragOff =
        (uint32_t)((wm + (lane & 7) + ((lane >> 3) & 1) * 8) * KSTRIDE
                   + ((lane >> 4) & 1) * 4);
    // B x4 @ (p,kk): matrices {rows 2p, kk},{2p, kk+4},{2p+1, kk},{2p+1, kk+4}
    const uint32_t bFragOff =
        (uint32_t)((wn + (lane & 7) + ((lane >> 4) & 1) * 8) * KSTRIDE
                   + ((lane >> 3) & 1) * 4)
        + A_STAGE_FLOATS;

    float c[4][4][4];
    #pragma unroll
    for (int mi = 0; mi < 4; mi++)
        #pragma unroll
        for (int ni = 0; ni < 4; ni++)
            #pragma unroll
            for (int r = 0; r < 4; r++) c[mi][ni][r] = 0.f;

    const int T = D / KT;

    #pragma unroll
    for (int p = 0; p < NSTAGE - 1; p++) {
        const float* an = a_src + p * KT;
        const float* bn = b_src + p * KT;
        cp16(aDst[p], an); cp16(aDst[p] + 16, an + 4);
        cp16(bDst[p], bn); cp16(bDst[p] + 16, bn + 4);
        asm volatile("cp.async.commit_group;");
    }

    for (int i = 0; i < T; i++) {
        asm volatile("cp.async.wait_group %0;" :: "n"(NSTAGE - 2));
        __syncthreads();   // also protects stage (i+3)%4, consumed at i-1

        // refill early, then compute
        const int nxt = i + NSTAGE - 1;
        if (nxt < T) {
            const int sn = nxt & (NSTAGE - 1);
            const float* an = a_src + nxt * KT;
            const float* bn = b_src + nxt * KT;
            cp16(aDst[sn], an); cp16(aDst[sn] + 16, an + 4);
            cp16(bDst[sn], bn); cp16(bDst[sn] + 16, bn + 4);
        }
        asm volatile("cp.async.commit_group;");

        const int s = i & (NSTAGE - 1);
        const uint32_t stage = smem_base + (uint32_t)(s * STAGE_FLOATS) * 4;
        const uint32_t aB = stage + aFragOff * 4;
        const uint32_t bB = stage + bFragOff * 4;

        #pragma unroll
        for (int kk = 0; kk < KT; kk += 8) {
            uint32_t af[4][4], bf[4][2];
            #pragma unroll
            for (int mi = 0; mi < 4; mi++)
                ldsm4(af[mi][0], af[mi][1], af[mi][2], af[mi][3],
                      aB + (uint32_t)(mi * 16 * KSTRIDE + kk) * 4);
            #pragma unroll
            for (int p = 0; p < 2; p++)
                ldsm4(bf[2*p][0], bf[2*p][1], bf[2*p+1][0], bf[2*p+1][1],
                      bB + (uint32_t)(p * 16 * KSTRIDE + kk) * 4);

            #pragma unroll
            for (int mi = 0; mi < 4; mi++)
                #pragma unroll
                for (int ni = 0; ni < 4; ni++)
                    asm volatile(
                        "mma.sync.aligned.m16n8k8.row.col.f32.tf32.tf32.f32 "
                        "{%0,%1,%2,%3}, {%4,%5,%6,%7}, {%8,%9}, {%0,%1,%2,%3};"
                        : "+f"(c[mi][ni][0]), "+f"(c[mi][ni][1]),
                          "+f"(c[mi][ni][2]), "+f"(c[mi][ni][3])
                        : "r"(af[mi][0]), "r"(af[mi][1]),
                          "r"(af[mi][2]), "r"(af[mi][3]),
                          "r"(bf[ni][0]), "r"(bf[ni][1]));
        }
    }

    // ---- fused epilogue: bias, exp-sum, target/gate logit gather ----------
    float bv[4][2];
    #pragma unroll
    for (int ni = 0; ni < 4; ni++)
        #pragma unroll
        for (int j = 0; j < 2; j++) {
            const int n = col_base + wn + ni * 8 + 2 * qcol + j;
            float b = 0.f;
            if (n < ncols) {
                if (cluster == 0) b = (n < S_SHORT) ? __ldg(&bias[n])
                                                    : __ldg(&cbias[n - S_SHORT]);
                else              b = __ldg(&bias[class_lo + n]);
            }
            bv[ni][j] = b;
        }

    #pragma unroll
    for (int mi = 0; mi < 4; mi++)
        #pragma unroll
        for (int h = 0; h < 2; h++) {
            const int m = row_base + wm + mi * 16 + qrow + h * 8;
            const bool valid = (m < count);
            int token = 0, needcol = -1;
            if (valid) {
                token   = (cluster == 0) ? m : g_list[(cluster - 1) * MAXNT + m];
                needcol = (cluster == 0) ? g_need[token] : g_localt[token];
            }
            float ssum = 0.f;
            #pragma unroll
            for (int ni = 0; ni < 4; ni++)
                #pragma unroll
                for (int j = 0; j < 2; j++) {
                    const int n = col_base + wn + ni * 8 + 2 * qcol + j;
                    if (n < ncols) {
                        const float z = c[mi][ni][h * 2 + j] + bv[ni][j];
                        ssum += __expf(z);
                        if (valid && n == needcol) {
                            if (cluster == 0) g_lg_head[token] = z;
                            else              g_lg_tail[token] = z;
                        }
                    }
                }
            ssum += __shfl_xor_sync(0xffffffffu, ssum, 1);
            ssum += __shfl_xor_sync(0xffffffffu, ssum, 2);
            if (valid && qcol == 0) {
                if (cluster == 0) atomicAdd(&g_se_head[token], ssum);
                else              atomicAdd(&g_se_tail[token], ssum);
            }
        }
}

// ----------------------------------------------------------------------------
__global__ void finalize_kernel(float* __restrict__ out, int NT)
{
    const int t = blockIdx.x * blockDim.x + threadIdx.x;
    if (t >= NT) return;
    float nll = logf(g_se_head[t]) - g_lg_head[t];
    if (g_cluster[t] > 0)
        nll += logf(g_se_tail[t]) - g_lg_tail[t];
    out[t] = nll;
}

// ----------------------------------------------------------------------------
extern "C" void kernel_launch(void* const* d_in, const int* in_sizes, int n_in,
                              void* d_out, int out_size)
{
    const float* hidden  = (const float*)d_in[0];
    const int*   traw    = (const int*)  d_in[1];
    const float* weight  = (const float*)d_in[2];
    const float* bias    = (const float*)d_in[3];
    const float* cweight = (const float*)d_in[4];
    const float* cbias   = (const float*)d_in[5];

    const int NT = out_size;
    const int D  = in_sizes[0] / NT;

    static bool attr_done = false;
    if (!attr_done) {
        cudaFuncSetAttribute(gemm_lse_tc,
                             cudaFuncAttributeMaxDynamicSharedMemorySize,
                             SMEM_BYTES);
        attr_done = true;
    }

    prep_kernel<<<1, 256>>>(traw, NT);

    const int gx = (NT + TM - 1) / TM;
    const int t0 = (S_SHORT + 3 + TN - 1) / TN;       // head col tiles
    const int t1 = (CUT1 - S_SHORT + TN - 1) / TN;
    const int t2 = (CUT2 - CUT1 + TN - 1) / TN;
    const int t3 = (NCLASS - CUT2 + TN - 1) / TN;
    const int e0 = gx * t0;
    const int e1 = e0 + gx * t1;
    const int e2 = e1 + gx * t2;
    const int e3 = e2 + gx * t3;

    gemm_lse_tc<<<e3, NTHREADS, SMEM_BYTES>>>(
        hidden, weight, bias, cweight, cbias, D, NT, gx, e0, e1, e2);

    finalize_kernel<<<(NT + 255) / 256, 256>>>((float*)d_out, NT);
}